// round 9
// baseline (speedup 1.0000x reference)
#include <cuda_runtime.h>
#include <cuda_bf16.h>
#include <math.h>

#define Bc 128
#define Pc 4096
#define Fc 32
#define Kc 8
#define Dc 64
#define ITERS_C 2

typedef unsigned long long ull;

// ---------------- scratch (static __device__, no runtime alloc) ----------------
__device__ ull g_kq[(size_t)Bc * 16 * Pc];     // K bf16 quads: [B][dquad 0..15][P]
__device__ ull g_vq[(size_t)Bc * Pc * 16];     // V bf16 quads: [B][P][dquad 0..15]
__device__ float g_slots[Bc * Kc * Dc];
__device__ float g_q[Bc * Kc * Dc];
__device__ float g_upd[Bc * Kc * Dc];
__device__ float g_S[Bc * Kc];
__device__ float g_WqT[Dc * Dc];               // [e][d]
__device__ float g_WihT[Dc * 3 * Dc];          // [e][j], stride 192
__device__ float g_WhhT[Dc * 3 * Dc];          // [e][j], stride 192
__device__ float g_W1T[Dc * 2 * Dc];           // [e][j], stride 128
__device__ float g_W2T[2 * Dc * Dc];           // [j][d], stride 64

// ---------------- packed helpers ----------------
__device__ __forceinline__ ull fma2(ull a, ull b, ull c) {
    ull d;
    asm("fma.rn.f32x2 %0, %1, %2, %3;" : "=l"(d) : "l"(a), "l"(b), "l"(c));
    return d;
}
__device__ __forceinline__ ull pack2(float x, float y) {
    ull r;
    asm("mov.b64 %0, {%1, %2};" : "=l"(r) : "f"(x), "f"(y));
    return r;
}
__device__ __forceinline__ float2 unpack2(ull v) {
    float2 r;
    asm("mov.b64 {%0, %1}, %2;" : "=f"(r.x), "=f"(r.y) : "l"(v));
    return r;
}
__device__ __forceinline__ unsigned bf2_of(float lo, float hi) {
    unsigned r;
    asm("cvt.rn.bf16x2.f32 %0, %1, %2;" : "=r"(r) : "f"(hi), "f"(lo));
    return r;
}
__device__ __forceinline__ ull packu(unsigned lo, unsigned hi) {
    ull r;
    asm("mov.b64 %0, {%1, %2};" : "=l"(r) : "r"(lo), "r"(hi));
    return r;
}
__device__ __forceinline__ void unpacku(ull v, unsigned& lo, unsigned& hi) {
    asm("mov.b64 {%0, %1}, %2;" : "=r"(lo), "=r"(hi) : "l"(v));
}
__device__ __forceinline__ float bflo(unsigned u) { return __uint_as_float(u << 16); }
__device__ __forceinline__ float bfhi(unsigned u) { return __uint_as_float(u & 0xffff0000u); }

// ---------------- init: slots init + weight transposes ----------------
__global__ void k_init(const float* __restrict__ noise, const float* __restrict__ mu,
                       const float* __restrict__ sigma, const float* __restrict__ Wq,
                       const float* __restrict__ Wih, const float* __restrict__ Whh,
                       const float* __restrict__ W1, const float* __restrict__ W2) {
    int i = blockIdx.x * blockDim.x + threadIdx.x;  // 0..65535
    if (i < Bc * Kc * Dc) {
        int d = i & 63;
        g_slots[i] = mu[d] + fabsf(sigma[d]) * noise[i];
    }
    if (i < Dc * Dc) {  // Wq [64,64] -> [e][d]
        g_WqT[(i & 63) * Dc + (i >> 6)] = Wq[i];
    }
    if (i < 3 * Dc * Dc) {  // [192,64] -> [e][j]
        int j = i >> 6, e = i & 63;
        g_WihT[e * 192 + j] = Wih[i];
        g_WhhT[e * 192 + j] = Whh[i];
    }
    if (i < 2 * Dc * Dc) {  // ff_W1 [128,64] -> [e][j]
        int j = i >> 6, e = i & 63;
        g_W1T[e * 128 + j] = W1[i];
    }
    if (i < 2 * Dc * Dc) {  // ff_W2 [64,128] -> [j][d]
        int dd = i >> 7, j = i & 127;
        g_W2T[j * 64 + dd] = W2[i];
    }
}

// ---------------- LayerNorm(x) + K/V projection (bf16 outputs), 2 px/thread ----------------
// dynamic smem layout:
//   [0, 16384)         sW[32][128]   ([f][0..63]=WkT, [f][64..127]=WvT)
//   [16384, 16512)     sg[32]
//   [16512, 16640)     sb[32]
//   [16640, 90368)     sv[512][18] ull  (V staging, padded rows, 16B-aligned)
#define PROJ_SMEM 90368
__global__ void __launch_bounds__(256) k_proj(const float* __restrict__ x,
                                              const float* __restrict__ Wk,
                                              const float* __restrict__ Wv,
                                              const float* __restrict__ lg,
                                              const float* __restrict__ lb) {
    extern __shared__ char dsm[];
    float (*sW)[128] = (float(*)[128])dsm;
    float* sg = (float*)(dsm + 16384);
    float* sb = (float*)(dsm + 16512);
    ull* sv = (ull*)(dsm + 16640);

    int t = threadIdx.x;
    for (int i = t; i < Dc * Fc; i += 256) {
        int d = i >> 5, f = i & 31;
        sW[f][d] = Wk[i];
        sW[f][64 + d] = Wv[i];
    }
    if (t < Fc) { sg[t] = lg[t]; sb[t] = lb[t]; }
    __syncthreads();

    size_t gpbase = (size_t)blockIdx.x * 512;
    size_t gp0 = gpbase + t;        // pixel A
    size_t gp1 = gpbase + t + 256;  // pixel B
    int b = (int)(gpbase >> 12);    // same batch for whole tile (4096 % 512 == 0)
    int p0 = (int)(gp0 & 4095);
    int p1 = p0 + 256;

    float xv0[32], xv1[32];
    {
        const float4* xr4 = (const float4*)(x + gp0 * Fc);
#pragma unroll
        for (int j = 0; j < 8; j++) {
            float4 q = xr4[j];
            xv0[4 * j] = q.x; xv0[4 * j + 1] = q.y; xv0[4 * j + 2] = q.z; xv0[4 * j + 3] = q.w;
        }
        float m = 0.f;
#pragma unroll
        for (int f = 0; f < 32; f++) m += xv0[f];
        m *= (1.f / 32.f);
        float var = 0.f;
#pragma unroll
        for (int f = 0; f < 32; f++) { float dv = xv0[f] - m; var += dv * dv; }
        float rstd = rsqrtf(var * (1.f / 32.f) + 1e-5f);
#pragma unroll
        for (int f = 0; f < 32; f++) xv0[f] = (xv0[f] - m) * rstd * sg[f] + sb[f];
    }
    {
        const float4* xr4 = (const float4*)(x + gp1 * Fc);
#pragma unroll
        for (int j = 0; j < 8; j++) {
            float4 q = xr4[j];
            xv1[4 * j] = q.x; xv1[4 * j + 1] = q.y; xv1[4 * j + 2] = q.z; xv1[4 * j + 3] = q.w;
        }
        float m = 0.f;
#pragma unroll
        for (int f = 0; f < 32; f++) m += xv1[f];
        m *= (1.f / 32.f);
        float var = 0.f;
#pragma unroll
        for (int f = 0; f < 32; f++) { float dv = xv1[f] - m; var += dv * dv; }
        float rstd = rsqrtf(var * (1.f / 32.f) + 1e-5f);
#pragma unroll
        for (int f = 0; f < 32; f++) xv1[f] = (xv1[f] - m) * rstd * sg[f] + sb[f];
    }

#pragma unroll
    for (int c = 0; c < 4; c++) {  // 4 chunks of 32 outputs (16 d-pairs), both pixels
        ull acc0[16], acc1[16];
#pragma unroll
        for (int j = 0; j < 16; j++) { acc0[j] = 0ULL; acc1[j] = 0ULL; }
#pragma unroll 2
        for (int f = 0; f < 32; f++) {
            ull xx0 = pack2(xv0[f], xv0[f]);
            ull xx1 = pack2(xv1[f], xv1[f]);
            const ulonglong2* w2 = (const ulonglong2*)&sW[f][32 * c];  // 8 x LDS.128 shared by 2 px
#pragma unroll
            for (int j = 0; j < 8; j++) {
                ulonglong2 wp = w2[j];
                acc0[2 * j] = fma2(xx0, wp.x, acc0[2 * j]);
                acc0[2 * j + 1] = fma2(xx0, wp.y, acc0[2 * j + 1]);
                acc1[2 * j] = fma2(xx1, wp.x, acc1[2 * j]);
                acc1[2 * j + 1] = fma2(xx1, wp.y, acc1[2 * j + 1]);
            }
        }
        if (c < 2) {  // K -> bf16 quads [B][16][P] (coalesced over p)
#pragma unroll
            for (int j = 0; j < 16; j += 2) {
                int q = 8 * c + (j >> 1);
                float2 r0 = unpack2(acc0[j]);
                float2 r1 = unpack2(acc0[j + 1]);
                g_kq[((size_t)b * 16 + q) * Pc + p0] = packu(bf2_of(r0.x, r0.y), bf2_of(r1.x, r1.y));
                float2 s0 = unpack2(acc1[j]);
                float2 s1 = unpack2(acc1[j + 1]);
                g_kq[((size_t)b * 16 + q) * Pc + p1] = packu(bf2_of(s0.x, s0.y), bf2_of(s1.x, s1.y));
            }
        } else {  // V -> stage quads in smem (coalesced flush below)
            int qb = (c - 2) * 8;  // quad base 0 or 8
#pragma unroll
            for (int j = 0; j < 16; j += 4) {
                float2 r0 = unpack2(acc0[j]);
                float2 r1 = unpack2(acc0[j + 1]);
                float2 r2 = unpack2(acc0[j + 2]);
                float2 r3 = unpack2(acc0[j + 3]);
                ulonglong2 qq;
                qq.x = packu(bf2_of(r0.x, r0.y), bf2_of(r1.x, r1.y));
                qq.y = packu(bf2_of(r2.x, r2.y), bf2_of(r3.x, r3.y));
                *(ulonglong2*)&sv[t * 18 + qb + (j >> 1)] = qq;
                float2 s0 = unpack2(acc1[j]);
                float2 s1 = unpack2(acc1[j + 1]);
                float2 s2 = unpack2(acc1[j + 2]);
                float2 s3 = unpack2(acc1[j + 3]);
                ulonglong2 pp;
                pp.x = packu(bf2_of(s0.x, s0.y), bf2_of(s1.x, s1.y));
                pp.y = packu(bf2_of(s2.x, s2.y), bf2_of(s3.x, s3.y));
                *(ulonglong2*)&sv[(t + 256) * 18 + qb + (j >> 1)] = pp;
            }
        }
    }
    __syncthreads();

    // flush V: 512 px * 16 quads = 4096 ulonglong2, fully coalesced STG.128
    ull* vout = (ull*)g_vq + gpbase * 16;
#pragma unroll
    for (int k = 0; k < 16; k++) {
        int i = t + 256 * k;          // 0..4095 (ulonglong2 index)
        int px = i >> 3, u = i & 7;
        ulonglong2 qq = *(const ulonglong2*)&sv[px * 18 + 2 * u];
        *(ulonglong2*)&vout[(size_t)px * 16 + 2 * u] = qq;
    }
}

// ---------------- q = LN(slots) @ Wq^T; zero S and upd (iter 0 only) ----------------
__global__ void k_q(const float* __restrict__ lsg, const float* __restrict__ lsb) {
    int row = blockIdx.x;  // b*K+s
    int d = threadIdx.x;   // 0..63
    __shared__ float sh[64];
    __shared__ float red[2], red2[2];
    float v = g_slots[row * 64 + d];
    float s1 = v;
#pragma unroll
    for (int o = 16; o > 0; o >>= 1) s1 += __shfl_xor_sync(0xffffffffu, s1, o);
    if ((d & 31) == 0) red[d >> 5] = s1;
    __syncthreads();
    float mean = (red[0] + red[1]) * (1.f / 64.f);
    float dv = v - mean;
    float s2 = dv * dv;
#pragma unroll
    for (int o = 16; o > 0; o >>= 1) s2 += __shfl_xor_sync(0xffffffffu, s2, o);
    if ((d & 31) == 0) red2[d >> 5] = s2;
    __syncthreads();
    float var = (red2[0] + red2[1]) * (1.f / 64.f);
    float rstd = rsqrtf(var + 1e-5f);
    sh[d] = dv * rstd * lsg[d] + lsb[d];
    __syncthreads();
    float acc = 0.f;
#pragma unroll 8
    for (int e = 0; e < 64; e++) acc += sh[e] * g_WqT[e * 64 + d];
    g_q[row * 64 + d] = acc;
    g_upd[row * 64 + d] = 0.f;
    if (d == 0) g_S[row] = 0.f;
}

// ---------------- dots + softmax(slots) + eps + S + unnormalized updates ----------------
// 2 pixels/thread; tile = 512 pixels; attn stored as plain float [512][8]
__global__ void __launch_bounds__(256) k_attn(float* __restrict__ out_attn, int last) {
    __shared__ ull sq2[32][8];       // q pairs: [dpair][slot], 2KB
    __shared__ float saf[512][8];    // attn floats, pixel-major (16KB, rows 32B -> float4 ok)
    __shared__ float supd[512];      // block-local update accumulator [s][64]
    int t = threadIdx.x;
    int b = blockIdx.x >> 3;
    int tile = blockIdx.x & 7;
    {
        int dp = t >> 3, s = t & 7;
        float q0 = g_q[b * 512 + s * 64 + 2 * dp];
        float q1 = g_q[b * 512 + s * 64 + 2 * dp + 1];
        sq2[dp][s] = pack2(q0, q1);
    }
    supd[t] = 0.f;
    supd[t + 256] = 0.f;
    __syncthreads();

    int px0 = tile * 512 + t;  // pixel A in batch; pixel B = px0 + 256
    const ull* kb = g_kq + (size_t)b * 16 * Pc + px0;

    // dots for 2 pixels: 32 LDG.64, q LDS.128 shared by both pixels
    ull acc0[8], acc1[8];
#pragma unroll
    for (int s = 0; s < 8; s++) { acc0[s] = 0ULL; acc1[s] = 0ULL; }
#pragma unroll
    for (int q = 0; q < 16; q++) {
        ull kv0 = __ldg(kb + (size_t)q * Pc);
        ull kv1 = __ldg(kb + (size_t)q * Pc + 256);
        unsigned lo0, hi0, lo1, hi1;
        unpacku(kv0, lo0, hi0);
        unpacku(kv1, lo1, hi1);
        ull k0A = pack2(bflo(lo0), bfhi(lo0));
        ull k0B = pack2(bflo(hi0), bfhi(hi0));
        ull k1A = pack2(bflo(lo1), bfhi(lo1));
        ull k1B = pack2(bflo(hi1), bfhi(hi1));
        const ulonglong2* qa = (const ulonglong2*)sq2[2 * q];
        const ulonglong2* qb4 = (const ulonglong2*)sq2[2 * q + 1];
#pragma unroll
        for (int j = 0; j < 4; j++) {
            ulonglong2 av = qa[j];
            ulonglong2 bv = qb4[j];
            acc0[2 * j] = fma2(k0A, av.x, acc0[2 * j]);
            acc0[2 * j + 1] = fma2(k0A, av.y, acc0[2 * j + 1]);
            acc0[2 * j] = fma2(k0B, bv.x, acc0[2 * j]);
            acc0[2 * j + 1] = fma2(k0B, bv.y, acc0[2 * j + 1]);
            acc1[2 * j] = fma2(k1A, av.x, acc1[2 * j]);
            acc1[2 * j + 1] = fma2(k1A, av.y, acc1[2 * j + 1]);
            acc1[2 * j] = fma2(k1B, bv.x, acc1[2 * j]);
            acc1[2 * j + 1] = fma2(k1B, bv.y, acc1[2 * j + 1]);
        }
    }

    float attn0[8], attn1[8];
    {
        float mx = -1e30f;
#pragma unroll
        for (int s = 0; s < 8; s++) {
            float2 r = unpack2(acc0[s]);
            attn0[s] = (r.x + r.y) * 0.125f;
            mx = fmaxf(mx, attn0[s]);
        }
        float sum = 0.f;
#pragma unroll
        for (int s = 0; s < 8; s++) { attn0[s] = __expf(attn0[s] - mx); sum += attn0[s]; }
        float inv = 1.f / sum;
#pragma unroll
        for (int s = 0; s < 8; s++) attn0[s] = attn0[s] * inv + 1e-8f;
    }
    {
        float mx = -1e30f;
#pragma unroll
        for (int s = 0; s < 8; s++) {
            float2 r = unpack2(acc1[s]);
            attn1[s] = (r.x + r.y) * 0.125f;
            mx = fmaxf(mx, attn1[s]);
        }
        float sum = 0.f;
#pragma unroll
        for (int s = 0; s < 8; s++) { attn1[s] = __expf(attn1[s] - mx); sum += attn1[s]; }
        float inv = 1.f / sum;
#pragma unroll
        for (int s = 0; s < 8; s++) attn1[s] = attn1[s] * inv + 1e-8f;
    }

    // store attn as plain floats (2x STS.128 per pixel)
    *(float4*)&saf[t][0] = make_float4(attn0[0], attn0[1], attn0[2], attn0[3]);
    *(float4*)&saf[t][4] = make_float4(attn0[4], attn0[5], attn0[6], attn0[7]);
    *(float4*)&saf[t + 256][0] = make_float4(attn1[0], attn1[1], attn1[2], attn1[3]);
    *(float4*)&saf[t + 256][4] = make_float4(attn1[4], attn1[5], attn1[6], attn1[7]);

    if (last) {
        float* ao = out_attn + (size_t)b * Kc * Pc + px0;
#pragma unroll
        for (int s = 0; s < 8; s++) {
            ao[(size_t)s * Pc] = attn0[s];
            ao[(size_t)s * Pc + 256] = attn1[s];
        }
    }

    int w = t >> 5, lane = t & 31;

    // S: shfl butterfly per slot (64 pixels per warp), one global atomic per (warp, slot)
#pragma unroll
    for (int s = 0; s < 8; s++) {
        float v = attn0[s] + attn1[s];
#pragma unroll
        for (int o = 16; o > 0; o >>= 1) v += __shfl_xor_sync(0xffffffffu, v, o);
        if (lane == 0) atomicAdd(&g_S[b * Kc + s], v);
    }
    __syncthreads();

    // updates: warp w covers 64 pixels (p0 = w*64); lane = d-pair; attn via uniform LDS.128
    int p0 = w * 64;
    const unsigned* vb = (const unsigned*)g_vq + ((size_t)b * Pc + tile * 512 + p0) * 32 + lane;
    ull ua[8];
#pragma unroll
    for (int s = 0; s < 8; s++) ua[s] = 0ULL;
#pragma unroll 8
    for (int i = 0; i < 64; i++) {
        unsigned u = __ldg(vb + i * 32);        // bf162 for d = 2*lane, 2*lane+1
        ull v2 = pack2(bflo(u), bfhi(u));
        float4 a03 = *(const float4*)&saf[p0 + i][0];
        float4 a47 = *(const float4*)&saf[p0 + i][4];
        ua[0] = fma2(pack2(a03.x, a03.x), v2, ua[0]);
        ua[1] = fma2(pack2(a03.y, a03.y), v2, ua[1]);
        ua[2] = fma2(pack2(a03.z, a03.z), v2, ua[2]);
        ua[3] = fma2(pack2(a03.w, a03.w), v2, ua[3]);
        ua[4] = fma2(pack2(a47.x, a47.x), v2, ua[4]);
        ua[5] = fma2(pack2(a47.y, a47.y), v2, ua[5]);
        ua[6] = fma2(pack2(a47.z, a47.z), v2, ua[6]);
        ua[7] = fma2(pack2(a47.w, a47.w), v2, ua[7]);
    }
#pragma unroll
    for (int s = 0; s < 8; s++) {
        float2 r = unpack2(ua[s]);
        atomicAdd(&supd[s * 64 + 2 * lane], r.x);
        atomicAdd(&supd[s * 64 + 2 * lane + 1], r.y);
    }
    __syncthreads();
    atomicAdd(&g_upd[b * 512 + t], supd[t]);
    atomicAdd(&g_upd[b * 512 + t + 256], supd[t + 256]);
}

// ---------------- GRU cell + LN + FF + residual (+ optional next-iter q) ----------------
__global__ void k_gru(const float* __restrict__ bih, const float* __restrict__ bhh,
                      const float* __restrict__ ffg, const float* __restrict__ ffb,
                      const float* __restrict__ fb1, const float* __restrict__ fb2,
                      const float* __restrict__ lsg, const float* __restrict__ lsb,
                      float* __restrict__ out_slots, int last) {
    int row = blockIdx.x;  // b*K+s
    int d = threadIdx.x;   // 0..63
    __shared__ float su[64], sp[64], sf[64], sr1[128];
    __shared__ float red[2], red2[2];

    float S = g_S[row];
    float u = g_upd[row * 64 + d] / S;
    float hp = g_slots[row * 64 + d];
    su[d] = u;
    sp[d] = hp;
    __syncthreads();

    float gir = bih[d], giz = bih[64 + d], gin = bih[128 + d];
    float ghr = bhh[d], ghz = bhh[64 + d], ghn = bhh[128 + d];
#pragma unroll 4
    for (int e = 0; e < 64; e++) {
        float ue = su[e], he = sp[e];
        const float* wi = g_WihT + e * 192 + d;
        const float* wh = g_WhhT + e * 192 + d;
        gir += ue * wi[0];
        giz += ue * wi[64];
        gin += ue * wi[128];
        ghr += he * wh[0];
        ghz += he * wh[64];
        ghn += he * wh[128];
    }
    float r = 1.f / (1.f + expf(-(gir + ghr)));
    float z = 1.f / (1.f + expf(-(giz + ghz)));
    float n = tanhf(gin + r * ghn);
    float h = (1.f - z) * n + z * hp;

    // LayerNorm(h)
    float s1 = h;
#pragma unroll
    for (int o = 16; o > 0; o >>= 1) s1 += __shfl_xor_sync(0xffffffffu, s1, o);
    if ((d & 31) == 0) red[d >> 5] = s1;
    __syncthreads();
    float mean = (red[0] + red[1]) * (1.f / 64.f);
    float dv = h - mean;
    float s2 = dv * dv;
#pragma unroll
    for (int o = 16; o > 0; o >>= 1) s2 += __shfl_xor_sync(0xffffffffu, s2, o);
    if ((d & 31) == 0) red2[d >> 5] = s2;
    __syncthreads();
    float var = (red2[0] + red2[1]) * (1.f / 64.f);
    float rstd = rsqrtf(var + 1e-5f);
    sf[d] = dv * rstd * ffg[d] + ffb[d];
    __syncthreads();

    // FF layer 1 (+ReLU)
    float a0 = fb1[d], a1 = fb1[64 + d];
#pragma unroll 8
    for (int e = 0; e < 64; e++) {
        float f = sf[e];
        a0 += f * g_W1T[e * 128 + d];
        a1 += f * g_W1T[e * 128 + 64 + d];
    }
    sr1[d] = fmaxf(a0, 0.f);
    sr1[64 + d] = fmaxf(a1, 0.f);
    __syncthreads();

    // FF layer 2 + residual
    float o = fb2[d];
#pragma unroll 8
    for (int j = 0; j < 128; j++) o += sr1[j] * g_W2T[j * 64 + d];
    float ns = h + o;
    g_slots[row * 64 + d] = ns;
    if (last) {
        out_slots[row * 64 + d] = ns;
        return;
    }

    // -------- fused: q for next iteration + reset accumulators --------
    float t1 = ns;
#pragma unroll
    for (int off = 16; off > 0; off >>= 1) t1 += __shfl_xor_sync(0xffffffffu, t1, off);
    if ((d & 31) == 0) red[d >> 5] = t1;
    __syncthreads();
    float qmean = (red[0] + red[1]) * (1.f / 64.f);
    float qdv = ns - qmean;
    float t2 = qdv * qdv;
#pragma unroll
    for (int off = 16; off > 0; off >>= 1) t2 += __shfl_xor_sync(0xffffffffu, t2, off);
    if ((d & 31) == 0) red2[d >> 5] = t2;
    __syncthreads();
    float qvar = (red2[0] + red2[1]) * (1.f / 64.f);
    float qrstd = rsqrtf(qvar + 1e-5f);
    sf[d] = qdv * qrstd * lsg[d] + lsb[d];
    __syncthreads();
    float qacc = 0.f;
#pragma unroll 8
    for (int e = 0; e < 64; e++) qacc += sf[e] * g_WqT[e * 64 + d];
    g_q[row * 64 + d] = qacc;
    g_upd[row * 64 + d] = 0.f;
    if (d == 0) g_S[row] = 0.f;
}

// ---------------- final attn normalization over pixels (vectorized) ----------------
__global__ void k_scale(float* __restrict__ out_attn) {
    size_t i = (size_t)blockIdx.x * 256 + threadIdx.x;  // float4 index < B*K*P/4
    int row = (int)((i * 4) >> 12);
    float inv = 1.f / g_S[row];
    float4* p4 = (float4*)out_attn;
    float4 v = p4[i];
    v.x *= inv; v.y *= inv; v.z *= inv; v.w *= inv;
    p4[i] = v;
}

// ---------------- launch ----------------
extern "C" void kernel_launch(void* const* d_in, const int* in_sizes, int n_in,
                              void* d_out, int out_size) {
    const float* x = (const float*)d_in[0];
    const float* noise = (const float*)d_in[1];
    const float* mu = (const float*)d_in[2];
    const float* sigma = (const float*)d_in[3];
    const float* Wq = (const float*)d_in[4];
    const float* Wk = (const float*)d_in[5];
    const float* Wv = (const float*)d_in[6];
    const float* Wih = (const float*)d_in[7];
    const float* Whh = (const float*)d_in[8];
    const float* bih = (const float*)d_in[9];
    const float* bhh = (const float*)d_in[10];
    const float* ling = (const float*)d_in[11];
    const float* linb = (const float*)d_in[12];
    const float* lsg = (const float*)d_in[13];
    const float* lsb = (const float*)d_in[14];
    const float* ffg = (const float*)d_in[15];
    const float* ffb = (const float*)d_in[16];
    const float* W1 = (const float*)d_in[17];
    const float* fb1 = (const float*)d_in[18];
    const float* W2 = (const float*)d_in[19];
    const float* fb2 = (const float*)d_in[20];

    float* out = (float*)d_out;
    float* out_slots = out;                     // [B,K,D]
    float* out_attn = out + Bc * Kc * Dc;       // [B,K,P]

    cudaFuncSetAttribute(k_proj, cudaFuncAttributeMaxDynamicSharedMemorySize, PROJ_SMEM);

    k_init<<<256, 256>>>(noise, mu, sigma, Wq, Wih, Whh, W1, W2);
    k_proj<<<(Bc * Pc) / 512, 256, PROJ_SMEM>>>(x, Wk, Wv, ling, linb);
    k_q<<<Bc * Kc, 64>>>(lsg, lsb);
    for (int it = 0; it < ITERS_C; it++) {
        int last = (it == ITERS_C - 1) ? 1 : 0;
        k_attn<<<(Bc * Pc) / 512, 256>>>(out_attn, last);
        k_gru<<<Bc * Kc, 64>>>(bih, bhh, ffg, ffb, fb1, fb2, lsg, lsb, out_slots, last);
    }
    k_scale<<<(Bc * Kc * Pc) / 1024, 256>>>(out_attn);
}